// round 1
// baseline (speedup 1.0000x reference)
#include <cuda_runtime.h>
#include <math.h>

// Problem constants (fixed by the reference setup_inputs)
#define BB      256
#define DIM     32768
#define SPLITS  128
#define CHUNK   (DIM / SPLITS)   // 256
#define TM      128
#define TN      128
#define MARGIN  0.003f

// Scratch (static __device__ arrays — no allocations anywhere)
__device__ float  g_partial[SPLITS * BB * BB];  // 32 MB split-K partials
__device__ float  g_G[BB * BB];                 // Gram matrix
__device__ double g_lossp[BB];                  // per-anchor loss partials
__device__ double g_cntp[BB];                   // per-anchor triple counts

// ---------------------------------------------------------------------------
// Kernel 1: split-K fp32 SIMT GEMM partials.  G_partial[s] = X[:, ks] X[:, ks]^T
// Grid: (BB/TN, BB/TM, SPLITS), 256 threads. Each thread owns an 8x8 microtile.
// No atomics -> deterministic.
// ---------------------------------------------------------------------------
__global__ __launch_bounds__(256) void gemm_partial_kernel(const float* __restrict__ X) {
    const int tile_n = blockIdx.x;
    const int tile_m = blockIdx.y;
    const int split  = blockIdx.z;
    const int t  = threadIdx.x;
    const int tx = t & 15;
    const int ty = t >> 4;

    __shared__ float As[8][TM + 4];
    __shared__ float Bs[8][TN + 4];

    float acc[8][8];
#pragma unroll
    for (int i = 0; i < 8; i++)
#pragma unroll
        for (int j = 0; j < 8; j++) acc[i][j] = 0.f;

    const int lrow = t >> 1;          // 0..127: row within tile loaded by this thread
    const int lcol = (t & 1) * 4;     // 0 or 4: float4 slot within 8-wide k panel
    const int ra   = tile_m * TM + lrow;
    const int rb   = tile_n * TN + lrow;
    const int k0   = split * CHUNK;

    for (int kc = 0; kc < CHUNK; kc += 8) {
        const int k = k0 + kc;
        // 16B-aligned vector loads (DIM and k are multiples of 8)
        float4 av = *reinterpret_cast<const float4*>(X + (size_t)ra * DIM + k + lcol);
        float4 bv = *reinterpret_cast<const float4*>(X + (size_t)rb * DIM + k + lcol);
        __syncthreads();   // previous iter's smem reads done before overwrite
        As[lcol + 0][lrow] = av.x; As[lcol + 1][lrow] = av.y;
        As[lcol + 2][lrow] = av.z; As[lcol + 3][lrow] = av.w;
        Bs[lcol + 0][lrow] = bv.x; Bs[lcol + 1][lrow] = bv.y;
        Bs[lcol + 2][lrow] = bv.z; Bs[lcol + 3][lrow] = bv.w;
        __syncthreads();
#pragma unroll
        for (int kk = 0; kk < 8; kk++) {
            float a[8], b[8];
#pragma unroll
            for (int i = 0; i < 8; i++) a[i] = As[kk][ty * 8 + i];
#pragma unroll
            for (int j = 0; j < 8; j++) b[j] = Bs[kk][tx * 8 + j];
#pragma unroll
            for (int i = 0; i < 8; i++)
#pragma unroll
                for (int j = 0; j < 8; j++)
                    acc[i][j] = fmaf(a[i], b[j], acc[i][j]);
        }
    }

    float* out = g_partial + (size_t)split * BB * BB;
#pragma unroll
    for (int i = 0; i < 8; i++) {
        const int r = tile_m * TM + ty * 8 + i;
#pragma unroll
        for (int j = 0; j < 8; j++) {
            const int c = tile_n * TN + tx * 8 + j;
            out[r * BB + c] = acc[i][j];
        }
    }
}

// ---------------------------------------------------------------------------
// Kernel 2: deterministic ordered reduction of split-K partials into g_G.
// ---------------------------------------------------------------------------
__global__ void reduce_kernel() {
    const int idx = blockIdx.x * blockDim.x + threadIdx.x;  // 0..65535
    float s = 0.f;
    for (int p = 0; p < SPLITS; p++) s += g_partial[p * BB * BB + idx];
    g_G[idx] = s;
}

// ---------------------------------------------------------------------------
// Kernel 3: per-anchor triplet loss.
// Identity: sum over i<j same-modality of [relu(D_ij - D_ik + m) + relu(D_ij - D_jk + m)]
//          = sum over ORDERED same-modality pairs (a,b), b!=a, impostors k of
//            relu(D_ab - D_ak + m);  n_it = count of such ordered triples.
// One block per anchor a; D-row built on the fly from g_G (diag = squared norms).
// Block-internal reduction is serial-by-thread-0 -> deterministic.
// ---------------------------------------------------------------------------
__global__ __launch_bounds__(256) void loss_kernel(const int* __restrict__ mods) {
    const int a = blockIdx.x;
    const int t = threadIdx.x;
    __shared__ float  Drow[BB];
    __shared__ int    smod[BB];
    __shared__ double sacc[BB];
    __shared__ double scnt[BB];

    smod[t] = mods[t];
    const float sqa = g_G[a * BB + a];
    const float sqb = g_G[t * BB + t];
    float d2 = sqa + sqb - 2.f * g_G[a * BB + t];
    d2 = fmaxf(d2, 0.f);
    Drow[t] = (d2 > 0.f) ? sqrtf(d2) : 0.f;
    __syncthreads();

    const int ma = smod[a];
    double acc = 0.0;
    double cnt = 0.0;
    if (t != a && smod[t] == ma) {           // b = t is a same-modality positive
        const float dab = Drow[t];
        for (int k = 0; k < BB; k++) {
            if (smod[k] != ma) {             // impostor
                const float v = dab - Drow[k] + MARGIN;
                if (v > 0.f) acc += (double)v;
                cnt += 1.0;
            }
        }
    }
    sacc[t] = acc;
    scnt[t] = cnt;
    __syncthreads();
    if (t == 0) {
        double L = 0.0, C = 0.0;
        for (int i = 0; i < BB; i++) { L += sacc[i]; C += scnt[i]; }
        g_lossp[a] = L;
        g_cntp[a]  = C;
    }
}

// ---------------------------------------------------------------------------
// Kernel 4: final ordered reduction + division.
// ---------------------------------------------------------------------------
__global__ void final_kernel(float* __restrict__ out) {
    double L = 0.0, C = 0.0;
    for (int i = 0; i < BB; i++) { L += g_lossp[i]; C += g_cntp[i]; }
    out[0] = (float)(L / C);
}

// ---------------------------------------------------------------------------
extern "C" void kernel_launch(void* const* d_in, const int* in_sizes, int n_in,
                              void* d_out, int out_size) {
    const float* X    = (const float*)d_in[0];   // batch_codes [256, 32768] fp32
    const int*   mods = (const int*)  d_in[1];   // modalities  [256] int32
    (void)in_sizes; (void)n_in; (void)out_size;

    dim3 grid(BB / TN, BB / TM, SPLITS);
    gemm_partial_kernel<<<grid, 256>>>(X);
    reduce_kernel<<<(BB * BB) / 256, 256>>>();
    loss_kernel<<<BB, 256>>>(mods);
    final_kernel<<<1, 1>>>((float*)d_out);
}

// round 4
// speedup vs baseline: 2.7218x; 2.7218x over previous
#include <cuda_runtime.h>
#include <cuda_bf16.h>
#include <math.h>
#include <stdint.h>

// ---------------------------------------------------------------------------
// Problem constants
// ---------------------------------------------------------------------------
#define BB       256
#define DIM      32768
#define SPLITS   32
#define CHUNK    (DIM / SPLITS)     // 1024
#define KB       32                 // k-block (bf16 cols per smem stage)
#define NKB      (CHUNK / KB)       // 32
#define STRIDE   80                 // smem row stride in bytes (64B data + 16B pad)
#define A_OFF    0
#define BH_OFF   (128 * STRIDE)     // 10240
#define BL_OFF   (2 * 128 * STRIDE) // 20480
#define STAGE    (3 * 128 * STRIDE) // 30720
#define SMEM_TOTAL (2 * STAGE)      // 61440
#define MARGIN   0.003f

// ---------------------------------------------------------------------------
// Static device scratch (no allocations anywhere)
// ---------------------------------------------------------------------------
__device__ float  g_part[SPLITS * BB * BB];   // 8 MB: per-split T = 0.5*hh + hi*lo^T
__device__ float  g_G[BB * BB];
__device__ double g_lossp[BB];
__device__ double g_cntp[BB];

// ---------------------------------------------------------------------------
// Helpers
// ---------------------------------------------------------------------------
__device__ __forceinline__ uint32_t smem_u32(const void* p) {
    uint32_t a;
    asm("{ .reg .u64 t; cvta.to.shared.u64 t, %1; cvt.u32.u64 %0, t; }" : "=r"(a) : "l"(p));
    return a;
}
// pack (x0 -> low half, x1 -> high half) as bf16x2
__device__ __forceinline__ uint32_t packbf(float x0, float x1) {
    uint32_t r;
    asm("cvt.rn.bf16x2.f32 %0, %1, %2;" : "=r"(r) : "f"(x1), "f"(x0));
    return r;
}
__device__ __forceinline__ void sts64(uint32_t a, uint32_t x, uint32_t y) {
    asm volatile("st.shared.v2.b32 [%0], {%1,%2};" :: "r"(a), "r"(x), "r"(y));
}
__device__ __forceinline__ void ldm_x4(uint32_t a, uint32_t& r0, uint32_t& r1,
                                       uint32_t& r2, uint32_t& r3) {
    asm volatile("ldmatrix.sync.aligned.m8n8.x4.shared.b16 {%0,%1,%2,%3}, [%4];"
                 : "=r"(r0), "=r"(r1), "=r"(r2), "=r"(r3) : "r"(a));
}
__device__ __forceinline__ void mma16816(float& c0, float& c1, float& c2, float& c3,
                                         uint32_t a0, uint32_t a1, uint32_t a2, uint32_t a3,
                                         uint32_t b0, uint32_t b1) {
    asm volatile(
        "mma.sync.aligned.m16n8k16.row.col.f32.bf16.bf16.f32 "
        "{%0,%1,%2,%3}, {%4,%5,%6,%7}, {%8,%9}, {%0,%1,%2,%3};"
        : "+f"(c0), "+f"(c1), "+f"(c2), "+f"(c3)
        : "r"(a0), "r"(a1), "r"(a2), "r"(a3), "r"(b0), "r"(b1));
}

// ---------------------------------------------------------------------------
// Kernel 1: split-K bf16 hi/lo GEMM via mma.sync, convert fused.
//   grid (SPLITS, 4): blockIdx.y -> (mt, nt) in 2x2 tiles of 128x128.
//   T_p[128,128] = 0.5 * Ahi*Bhi^T + Ahi*Blo^T over this split's K-chunk.
//   8 warps in 2x4 layout, each owns a 64x32 region (4x4 m16n8 tiles).
// ---------------------------------------------------------------------------
extern __shared__ unsigned char dsm[];

__global__ __launch_bounds__(256, 1) void gemm_kernel(const float* __restrict__ X) {
    const int split = blockIdx.x;
    const int mt = blockIdx.y & 1;
    const int nt = blockIdx.y >> 1;
    const int t    = threadIdx.x;
    const int w    = t >> 5;
    const int lane = t & 31;
    const int wm   = w >> 2;      // 0..1
    const int wn   = w & 3;       // 0..3

    const uint32_t sb = smem_u32(dsm);
    const int chunk0 = split * CHUNK;

    // LDG mapping: each thread loads 4 float4 per side per k-block.
    const int lrow  = t >> 1;          // 0..127
    const int cpair = t & 1;           // 0/1 -> 16-col halves
    const float* pa = X + (size_t)(mt * 128 + lrow) * DIM + chunk0 + cpair * 16;
    const float* pb = X + (size_t)(nt * 128 + lrow) * DIM + chunk0 + cpair * 16;

    float acc[4][4][4];
#pragma unroll
    for (int i = 0; i < 4; i++)
#pragma unroll
        for (int j = 0; j < 4; j++)
#pragma unroll
            for (int r = 0; r < 4; r++) acc[i][j][r] = 0.f;

    float4 a4[4], b4[4];
    // prologue: load k-block 0
#pragma unroll
    for (int i = 0; i < 4; i++) {
        a4[i] = *reinterpret_cast<const float4*>(pa + i * 4);
        b4[i] = *reinterpret_cast<const float4*>(pb + i * 4);
    }
    // convert + store to stage 0
    {
        const uint32_t soff = lrow * STRIDE + cpair * 32;
#pragma unroll
        for (int i = 0; i < 4; i++) {
            float ax[4] = {a4[i].x, a4[i].y, a4[i].z, a4[i].w};
            float bx[4] = {b4[i].x, b4[i].y, b4[i].z, b4[i].w};
            uint32_t ah0 = packbf(ax[0], ax[1]);
            uint32_t ah1 = packbf(ax[2], ax[3]);
            sts64(sb + A_OFF + soff + i * 8, ah0, ah1);
            float bh[4], bl[4];
#pragma unroll
            for (int q = 0; q < 4; q++) {
                float h = __bfloat162float(__float2bfloat16(bx[q]));
                bh[q] = 0.5f * h;
                bl[q] = bx[q] - h;
            }
            sts64(sb + BH_OFF + soff + i * 8, packbf(bh[0], bh[1]), packbf(bh[2], bh[3]));
            sts64(sb + BL_OFF + soff + i * 8, packbf(bl[0], bl[1]), packbf(bl[2], bl[3]));
        }
    }

    // ldmatrix address components (stage-relative)
    const uint32_t a_ld = (uint32_t)(wm * 64 + (lane & 15)) * STRIDE + ((lane >> 4) & 1) * 16;
    const int bsel  = (lane >> 3) & 3;
    const uint32_t b_ld = (uint32_t)(wn * 32 + ((bsel >> 1) * 8) + (lane & 7)) * STRIDE
                        + (bsel & 1) * 16;

    for (int kb = 0; kb < NKB; kb++) {
        const int s = kb & 1;
        const uint32_t st = sb + s * STAGE;

        // prefetch next k-block (global loads issue now, consumed after mma)
        if (kb + 1 < NKB) {
            const int kcol = (kb + 1) * KB;
#pragma unroll
            for (int i = 0; i < 4; i++) {
                a4[i] = *reinterpret_cast<const float4*>(pa + kcol + i * 4);
                b4[i] = *reinterpret_cast<const float4*>(pb + kcol + i * 4);
            }
        }

        __syncthreads();   // stage s fully written

#pragma unroll
        for (int ks = 0; ks < 2; ks++) {
            const uint32_t ko = ks * 32;
            uint32_t af[4][4];
#pragma unroll
            for (int i = 0; i < 4; i++)
                ldm_x4(st + A_OFF + a_ld + (uint32_t)i * 16 * STRIDE + ko,
                       af[i][0], af[i][1], af[i][2], af[i][3]);
            uint32_t bhf[2][4], blf[2][4];
#pragma unroll
            for (int p = 0; p < 2; p++) {
                ldm_x4(st + BH_OFF + b_ld + (uint32_t)p * 16 * STRIDE + ko,
                       bhf[p][0], bhf[p][1], bhf[p][2], bhf[p][3]);
                ldm_x4(st + BL_OFF + b_ld + (uint32_t)p * 16 * STRIDE + ko,
                       blf[p][0], blf[p][1], blf[p][2], blf[p][3]);
            }
#pragma unroll
            for (int i = 0; i < 4; i++)
#pragma unroll
                for (int j = 0; j < 4; j++) {
                    const int p = j >> 1, h = (j & 1) * 2;
                    mma16816(acc[i][j][0], acc[i][j][1], acc[i][j][2], acc[i][j][3],
                             af[i][0], af[i][1], af[i][2], af[i][3],
                             bhf[p][h], bhf[p][h + 1]);
                    mma16816(acc[i][j][0], acc[i][j][1], acc[i][j][2], acc[i][j][3],
                             af[i][0], af[i][1], af[i][2], af[i][3],
                             blf[p][h], blf[p][h + 1]);
                }
        }

        // store prefetched block into the other stage
        if (kb + 1 < NKB) {
            const uint32_t st2 = sb + (s ^ 1) * STAGE;
            const uint32_t soff = lrow * STRIDE + cpair * 32;
#pragma unroll
            for (int i = 0; i < 4; i++) {
                float ax[4] = {a4[i].x, a4[i].y, a4[i].z, a4[i].w};
                float bx[4] = {b4[i].x, b4[i].y, b4[i].z, b4[i].w};
                sts64(st2 + A_OFF + soff + i * 8, packbf(ax[0], ax[1]), packbf(ax[2], ax[3]));
                float bh[4], bl[4];
#pragma unroll
                for (int q = 0; q < 4; q++) {
                    float h = __bfloat162float(__float2bfloat16(bx[q]));
                    bh[q] = 0.5f * h;
                    bl[q] = bx[q] - h;
                }
                sts64(st2 + BH_OFF + soff + i * 8, packbf(bh[0], bh[1]), packbf(bh[2], bh[3]));
                sts64(st2 + BL_OFF + soff + i * 8, packbf(bl[0], bl[1]), packbf(bl[2], bl[3]));
            }
        }
    }

    // Epilogue: write T partial. C frag: c0,c1 -> row lane/4, cols (lane%4)*2;
    // c2,c3 -> row lane/4 + 8.
    float* out = g_part + ((size_t)split << 16);
    const int rbase = mt * 128 + wm * 64 + (lane >> 2);
    const int cbase = nt * 128 + wn * 32 + (lane & 3) * 2;
#pragma unroll
    for (int i = 0; i < 4; i++)
#pragma unroll
        for (int j = 0; j < 4; j++) {
            const int r0 = rbase + i * 16;
            const int c  = cbase + j * 8;
            *reinterpret_cast<float2*>(out + r0 * BB + c)       = make_float2(acc[i][j][0], acc[i][j][1]);
            *reinterpret_cast<float2*>(out + (r0 + 8) * BB + c) = make_float2(acc[i][j][2], acc[i][j][3]);
        }
}

// ---------------------------------------------------------------------------
// Kernel 2: G = sum_p (T_p + T_p^T), fully coalesced via smem transpose.
// grid 64 = 8x8 tiles of 32x32; 256 threads: r = t/8, c4 = (t%8)*4.
// ---------------------------------------------------------------------------
__global__ __launch_bounds__(256) void reduce_kernel() {
    const int bi = blockIdx.x >> 3;
    const int bj = blockIdx.x & 7;
    const int t  = threadIdx.x;
    const int r  = t >> 3;
    const int c4 = (t & 7) * 4;

    float4 acc1 = make_float4(0.f, 0.f, 0.f, 0.f);
    float4 acc2 = make_float4(0.f, 0.f, 0.f, 0.f);
    for (int p = 0; p < SPLITS; p++) {
        const float* T = g_part + ((size_t)p << 16);
        float4 v1 = *reinterpret_cast<const float4*>(T + (bi * 32 + r) * BB + bj * 32 + c4);
        float4 v2 = *reinterpret_cast<const float4*>(T + (bj * 32 + r) * BB + bi * 32 + c4);
        acc1.x += v1.x; acc1.y += v1.y; acc1.z += v1.z; acc1.w += v1.w;
        acc2.x += v2.x; acc2.y += v2.y; acc2.z += v2.z; acc2.w += v2.w;
    }
    __shared__ float s2[32][33];
    s2[r][c4 + 0] = acc2.x; s2[r][c4 + 1] = acc2.y;
    s2[r][c4 + 2] = acc2.z; s2[r][c4 + 3] = acc2.w;
    __syncthreads();
    float4 gv;
    gv.x = acc1.x + s2[c4 + 0][r];
    gv.y = acc1.y + s2[c4 + 1][r];
    gv.z = acc1.z + s2[c4 + 2][r];
    gv.w = acc1.w + s2[c4 + 3][r];
    *reinterpret_cast<float4*>(g_G + (bi * 32 + r) * BB + bj * 32 + c4) = gv;
}

// ---------------------------------------------------------------------------
// Kernel 3: per-anchor triplet loss (ordered-pair identity), tree-reduced.
// sum over i<j same-mod of relu(D_ij-D_ik+m)+relu(D_ij-D_jk+m)
//   == sum over ORDERED same-mod pairs (a,b), impostors k of relu(D_ab-D_ak+m)
// ---------------------------------------------------------------------------
__global__ __launch_bounds__(256) void loss_kernel(const int* __restrict__ mods) {
    const int a = blockIdx.x;
    const int t = threadIdx.x;
    __shared__ float  Drow[BB];
    __shared__ int    smod[BB];
    __shared__ double sacc[BB];
    __shared__ double scnt[BB];

    smod[t] = mods[t];
    const float sqa = g_G[a * BB + a];
    const float sqb = g_G[t * BB + t];
    float d2 = sqa + sqb - 2.f * g_G[a * BB + t];
    d2 = fmaxf(d2, 0.f);
    Drow[t] = (d2 > 0.f) ? sqrtf(d2) : 0.f;
    __syncthreads();

    const int ma = smod[a];
    double acc = 0.0, cnt = 0.0;
    if (t != a && smod[t] == ma) {
        const float dab = Drow[t];
        for (int k = 0; k < BB; k++) {
            if (smod[k] != ma) {
                const float v = dab - Drow[k] + MARGIN;
                if (v > 0.f) acc += (double)v;
                cnt += 1.0;
            }
        }
    }
    sacc[t] = acc;
    scnt[t] = cnt;
    __syncthreads();
    for (int stride = 128; stride > 0; stride >>= 1) {
        if (t < stride) { sacc[t] += sacc[t + stride]; scnt[t] += scnt[t + stride]; }
        __syncthreads();
    }
    if (t == 0) { g_lossp[a] = sacc[0]; g_cntp[a] = scnt[0]; }
}

// ---------------------------------------------------------------------------
// Kernel 4: final tree reduction + division
// ---------------------------------------------------------------------------
__global__ __launch_bounds__(256) void final_kernel(float* __restrict__ out) {
    const int t = threadIdx.x;
    __shared__ double sL[BB];
    __shared__ double sC[BB];
    sL[t] = g_lossp[t];
    sC[t] = g_cntp[t];
    __syncthreads();
    for (int stride = 128; stride > 0; stride >>= 1) {
        if (t < stride) { sL[t] += sL[t + stride]; sC[t] += sC[t + stride]; }
        __syncthreads();
    }
    if (t == 0) out[0] = (float)(sL[0] / sC[0]);
}

// ---------------------------------------------------------------------------
extern "C" void kernel_launch(void* const* d_in, const int* in_sizes, int n_in,
                              void* d_out, int out_size) {
    const float* X    = (const float*)d_in[0];
    const int*   mods = (const int*)  d_in[1];
    (void)in_sizes; (void)n_in; (void)out_size;

    cudaFuncSetAttribute(gemm_kernel, cudaFuncAttributeMaxDynamicSharedMemorySize, SMEM_TOTAL);

    gemm_kernel<<<dim3(SPLITS, 4), 256, SMEM_TOTAL>>>(X);
    reduce_kernel<<<64, 256>>>();
    loss_kernel<<<BB, 256>>>(mods);
    final_kernel<<<1, 256>>>((float*)d_out);
}

// round 5
// speedup vs baseline: 4.0649x; 1.4934x over previous
#include <cuda_runtime.h>
#include <cuda_fp16.h>
#include <math.h>
#include <stdint.h>

// ---------------------------------------------------------------------------
// Problem constants
// ---------------------------------------------------------------------------
#define BB       256
#define DIM      32768
#define SPLITS   32
#define CHUNK    (DIM / SPLITS)     // 1024 fp16 cols per split
#define KB       64                 // k-block (fp16 cols per smem stage) = 128 B/row
#define NKB      (CHUNK / KB)       // 16
#define STRIDE   144                // smem row stride (128 B data + 16 B pad)
#define TILE_SM  (128 * STRIDE)     // 18432 B per tile
#define STAGE    (2 * TILE_SM)      // 36864 B (A tile + B tile)
#define NSTAGE   3
#define SMEM_TOTAL (NSTAGE * STAGE) // 110592 B
#define MARGIN   0.003f

// ---------------------------------------------------------------------------
// Static device scratch (no allocations anywhere)
// ---------------------------------------------------------------------------
__device__ __align__(16) __half g_h[BB * DIM];     // 16 MB fp16 copy of X
__device__ float  g_part[SPLITS * BB * BB];        // 8 MB split-K partials
__device__ float  g_G[BB * BB];
__device__ double g_lossp[BB];
__device__ double g_cntp[BB];
__device__ int    g_count;

// ---------------------------------------------------------------------------
// Helpers
// ---------------------------------------------------------------------------
__device__ __forceinline__ uint32_t smem_u32(const void* p) {
    uint32_t a;
    asm("{ .reg .u64 t; cvta.to.shared.u64 t, %1; cvt.u32.u64 %0, t; }" : "=r"(a) : "l"(p));
    return a;
}
__device__ __forceinline__ void cpasync16(uint32_t s, const void* g) {
    asm volatile("cp.async.cg.shared.global [%0], [%1], 16;" :: "r"(s), "l"(g) : "memory");
}
__device__ __forceinline__ void ldm_x4(uint32_t a, uint32_t& r0, uint32_t& r1,
                                       uint32_t& r2, uint32_t& r3) {
    asm volatile("ldmatrix.sync.aligned.m8n8.x4.shared.b16 {%0,%1,%2,%3}, [%4];"
                 : "=r"(r0), "=r"(r1), "=r"(r2), "=r"(r3) : "r"(a));
}
__device__ __forceinline__ void mma16816(float& c0, float& c1, float& c2, float& c3,
                                         uint32_t a0, uint32_t a1, uint32_t a2, uint32_t a3,
                                         uint32_t b0, uint32_t b1) {
    asm volatile(
        "mma.sync.aligned.m16n8k16.row.col.f32.f16.f16.f32 "
        "{%0,%1,%2,%3}, {%4,%5,%6,%7}, {%8,%9}, {%0,%1,%2,%3};"
        : "+f"(c0), "+f"(c1), "+f"(c2), "+f"(c3)
        : "r"(a0), "r"(a1), "r"(a2), "r"(a3), "r"(b0), "r"(b1));
}

// ---------------------------------------------------------------------------
// Kernel 1: fp32 -> fp16 convert (row-major, cp.async-ready)
// ---------------------------------------------------------------------------
__global__ __launch_bounds__(256) void convert_kernel(const float* __restrict__ X) {
    const int gid = blockIdx.x * 256 + threadIdx.x;      // < 1048576 (8 elts each)
    const float4* s = reinterpret_cast<const float4*>(X) + (size_t)gid * 2;
    const float4 a = s[0];
    const float4 b = s[1];
    __half2 h0 = __floats2half2_rn(a.x, a.y);
    __half2 h1 = __floats2half2_rn(a.z, a.w);
    __half2 h2 = __floats2half2_rn(b.x, b.y);
    __half2 h3 = __floats2half2_rn(b.z, b.w);
    uint4 v;
    v.x = *reinterpret_cast<uint32_t*>(&h0);
    v.y = *reinterpret_cast<uint32_t*>(&h1);
    v.z = *reinterpret_cast<uint32_t*>(&h2);
    v.w = *reinterpret_cast<uint32_t*>(&h3);
    reinterpret_cast<uint4*>(g_h)[gid] = v;
}

// ---------------------------------------------------------------------------
// Kernel 2: split-K fp16 GEMM, cp.async 3-stage pipeline.
//   grid (SPLITS, 4): blockIdx.y -> (mt, nt) 2x2 tiles of 128x128.
//   U_p[tile] = A_h * B_h^T over this split's K-chunk (fp32 accumulate).
//   8 warps (2x4), each owns 64x32 (4x4 m16n8 tiles).
// ---------------------------------------------------------------------------
extern __shared__ unsigned char dsm[];

__global__ __launch_bounds__(256, 1) void gemm_kernel() {
    const int split = blockIdx.x;
    const int mt = blockIdx.y & 1;
    const int nt = blockIdx.y >> 1;
    const int t    = threadIdx.x;
    const int w    = t >> 5;
    const int lane = t & 31;
    const int wm   = w >> 2;      // 0..1
    const int wn   = w & 3;       // 0..3

    const uint32_t sb = smem_u32(dsm);
    const int chunk0 = split * CHUNK;

    // cp.async mapping: 2048 x 16B segments per stage, 8 per thread
    const __half* gA = g_h + (size_t)(mt * 128) * DIM + chunk0;
    const __half* gB = g_h + (size_t)(nt * 128) * DIM + chunk0;

    float acc[4][4][4];
#pragma unroll
    for (int i = 0; i < 4; i++)
#pragma unroll
        for (int j = 0; j < 4; j++)
#pragma unroll
            for (int r = 0; r < 4; r++) acc[i][j][r] = 0.f;

    // issue all loads for k-block kb into stage st_idx
    auto issue = [&](int kb, int st_idx) {
        const uint32_t st = sb + st_idx * STAGE;
        const int kcol = kb * KB;
#pragma unroll
        for (int i = 0; i < 8; i++) {
            const int idx  = t + 256 * i;
            const int tile = idx >> 10;          // 0 = A, 1 = B
            const int s2   = idx & 1023;
            const int row  = s2 >> 3;
            const int c    = s2 & 7;
            const __half* g = (tile ? gB : gA) + (size_t)row * DIM + kcol + c * 8;
            cpasync16(st + tile * TILE_SM + row * STRIDE + c * 16, g);
        }
        asm volatile("cp.async.commit_group;" ::: "memory");
    };

    issue(0, 0);
    issue(1, 1);

    // ldmatrix address components (stage-relative)
    const uint32_t a_ld = (uint32_t)(wm * 64 + (lane & 15)) * STRIDE + ((lane >> 4) & 1) * 16;
    const int bsel  = (lane >> 3) & 3;
    const uint32_t b_ld = (uint32_t)(wn * 32 + ((bsel >> 1) * 8) + (lane & 7)) * STRIDE
                        + (bsel & 1) * 16;

    int st_idx = 0;
    for (int kb = 0; kb < NKB; kb++) {
        if (kb + 2 < NKB) {
            issue(kb + 2, (st_idx + 2) % NSTAGE);
            asm volatile("cp.async.wait_group 2;" ::: "memory");
        } else if (kb + 1 < NKB) {
            asm volatile("cp.async.wait_group 1;" ::: "memory");
        } else {
            asm volatile("cp.async.wait_group 0;" ::: "memory");
        }
        __syncthreads();   // stage st_idx complete for all; also fences prior reads

        const uint32_t st = sb + st_idx * STAGE;
#pragma unroll
        for (int ks = 0; ks < 4; ks++) {
            const uint32_t ko = ks * 32;
            uint32_t af[4][4];
#pragma unroll
            for (int i = 0; i < 4; i++)
                ldm_x4(st + a_ld + (uint32_t)i * 16 * STRIDE + ko,
                       af[i][0], af[i][1], af[i][2], af[i][3]);
            uint32_t bf[2][4];
#pragma unroll
            for (int p = 0; p < 2; p++)
                ldm_x4(st + TILE_SM + b_ld + (uint32_t)p * 16 * STRIDE + ko,
                       bf[p][0], bf[p][1], bf[p][2], bf[p][3]);
#pragma unroll
            for (int i = 0; i < 4; i++)
#pragma unroll
                for (int j = 0; j < 4; j++) {
                    const int p = j >> 1, h = (j & 1) * 2;
                    mma16816(acc[i][j][0], acc[i][j][1], acc[i][j][2], acc[i][j][3],
                             af[i][0], af[i][1], af[i][2], af[i][3],
                             bf[p][h], bf[p][h + 1]);
                }
        }
        st_idx = (st_idx + 1) % NSTAGE;
    }

    // Epilogue: write U partial. C frag: c0,c1 -> row lane/4, cols (lane%4)*2;
    // c2,c3 -> row +8.
    float* out = g_part + ((size_t)split << 16);
    const int rbase = mt * 128 + wm * 64 + (lane >> 2);
    const int cbase = nt * 128 + wn * 32 + (lane & 3) * 2;
#pragma unroll
    for (int i = 0; i < 4; i++)
#pragma unroll
        for (int j = 0; j < 4; j++) {
            const int r0 = rbase + i * 16;
            const int c  = cbase + j * 8;
            *reinterpret_cast<float2*>(out + r0 * BB + c)       = make_float2(acc[i][j][0], acc[i][j][1]);
            *reinterpret_cast<float2*>(out + (r0 + 8) * BB + c) = make_float2(acc[i][j][2], acc[i][j][3]);
        }
}

// ---------------------------------------------------------------------------
// Kernel 3: G = sum_p U_p (ordered, deterministic); also resets g_count.
// ---------------------------------------------------------------------------
__global__ __launch_bounds__(256) void reduce_kernel() {
    const int idx = blockIdx.x * 256 + threadIdx.x;     // 0..16383 (float4 units)
    float4 acc = make_float4(0.f, 0.f, 0.f, 0.f);
    for (int p = 0; p < SPLITS; p++) {
        float4 v = reinterpret_cast<const float4*>(g_part + ((size_t)p << 16))[idx];
        acc.x += v.x; acc.y += v.y; acc.z += v.z; acc.w += v.w;
    }
    reinterpret_cast<float4*>(g_G)[idx] = acc;
    if (idx == 0) g_count = 0;
}

// ---------------------------------------------------------------------------
// Kernel 4: per-anchor triplet loss (ordered-pair identity) + fused final
// reduction via last-block election (deterministic ordered tree reduce).
// Identity: sum over i<j same-mod of relu(D_ij-D_ik+m)+relu(D_ij-D_jk+m)
//   == sum over ORDERED same-mod pairs (a,b), impostors k of relu(D_ab-D_ak+m)
// ---------------------------------------------------------------------------
__global__ __launch_bounds__(256) void loss_kernel(const int* __restrict__ mods,
                                                   float* __restrict__ out) {
    const int a = blockIdx.x;
    const int t = threadIdx.x;
    __shared__ float  Drow[BB];
    __shared__ int    smod[BB];
    __shared__ double sacc[BB];
    __shared__ double scnt[BB];
    __shared__ int    is_last;

    smod[t] = mods[t];
    const float sqa = g_G[a * BB + a];
    const float sqb = g_G[t * BB + t];
    float d2 = sqa + sqb - 2.f * g_G[a * BB + t];
    d2 = fmaxf(d2, 0.f);
    Drow[t] = (d2 > 0.f) ? sqrtf(d2) : 0.f;
    __syncthreads();

    const int ma = smod[a];
    double acc = 0.0, cnt = 0.0;
    if (t != a && smod[t] == ma) {
        const float dab = Drow[t];
        for (int k = 0; k < BB; k++) {
            if (smod[k] != ma) {
                const float v = dab - Drow[k] + MARGIN;
                if (v > 0.f) acc += (double)v;
                cnt += 1.0;
            }
        }
    }
    sacc[t] = acc;
    scnt[t] = cnt;
    __syncthreads();
    for (int stride = 128; stride > 0; stride >>= 1) {
        if (t < stride) { sacc[t] += sacc[t + stride]; scnt[t] += scnt[t + stride]; }
        __syncthreads();
    }
    if (t == 0) { g_lossp[a] = sacc[0]; g_cntp[a] = scnt[0]; }

    // last-block-done election (threadFenceReduction pattern)
    __threadfence();
    if (t == 0) {
        int old = atomicAdd(&g_count, 1);
        is_last = (old == BB - 1);
    }
    __syncthreads();
    if (is_last) {
        __threadfence();
        sacc[t] = g_lossp[t];
        scnt[t] = g_cntp[t];
        __syncthreads();
        for (int stride = 128; stride > 0; stride >>= 1) {
            if (t < stride) { sacc[t] += sacc[t + stride]; scnt[t] += scnt[t + stride]; }
            __syncthreads();
        }
        if (t == 0) out[0] = (float)(sacc[0] / scnt[0]);
    }
}

// ---------------------------------------------------------------------------
extern "C" void kernel_launch(void* const* d_in, const int* in_sizes, int n_in,
                              void* d_out, int out_size) {
    const float* X    = (const float*)d_in[0];
    const int*   mods = (const int*)  d_in[1];
    (void)in_sizes; (void)n_in; (void)out_size;

    cudaFuncSetAttribute(gemm_kernel, cudaFuncAttributeMaxDynamicSharedMemorySize, SMEM_TOTAL);

    convert_kernel<<<(BB * DIM / 8) / 256, 256>>>(X);
    gemm_kernel<<<dim3(SPLITS, 4), 256, SMEM_TOTAL>>>();
    reduce_kernel<<<(BB * BB / 4) / 256, 256>>>();
    loss_kernel<<<BB, 256>>>(mods, (float*)d_out);
}

// round 6
// speedup vs baseline: 4.8369x; 1.1899x over previous
#include <cuda_runtime.h>
#include <cuda_fp16.h>
#include <math.h>
#include <stdint.h>

// ---------------------------------------------------------------------------
// Problem constants
// ---------------------------------------------------------------------------
#define BB       256
#define DIM      32768
#define SPLITS   32
#define CHUNK    (DIM / SPLITS)     // 1024 fp16 cols per split
#define KB       64                 // k-block (fp16 cols per smem stage) = 128 B/row
#define NKB      (CHUNK / KB)       // 16
#define STRIDE   144                // smem row stride (128 B data + 16 B pad)
#define TILE_SM  (128 * STRIDE)     // 18432 B per tile
#define STAGE    (2 * TILE_SM)      // 36864 B (A tile + B tile)
#define NSTAGE   3
#define SMEM_TOTAL (NSTAGE * STAGE) // 110592 B
#define MARGIN   0.003f

// ---------------------------------------------------------------------------
// Static device scratch (no allocations anywhere)
// ---------------------------------------------------------------------------
__device__ __align__(16) __half g_h[BB * DIM];     // 16 MB fp16 copy of X
__device__ float  g_part[SPLITS * BB * BB];        // 8 MB split-K partials
__device__ float  g_G[BB * BB];
__device__ double g_lossp[BB];
__device__ double g_cntp[BB];
__device__ int    g_count;

// ---------------------------------------------------------------------------
// Helpers
// ---------------------------------------------------------------------------
__device__ __forceinline__ uint32_t smem_u32(const void* p) {
    uint32_t a;
    asm("{ .reg .u64 t; cvta.to.shared.u64 t, %1; cvt.u32.u64 %0, t; }" : "=r"(a) : "l"(p));
    return a;
}
__device__ __forceinline__ void cpasync16(uint32_t s, const void* g) {
    asm volatile("cp.async.cg.shared.global [%0], [%1], 16;" :: "r"(s), "l"(g) : "memory");
}
__device__ __forceinline__ void ldm_x4(uint32_t a, uint32_t& r0, uint32_t& r1,
                                       uint32_t& r2, uint32_t& r3) {
    asm volatile("ldmatrix.sync.aligned.m8n8.x4.shared.b16 {%0,%1,%2,%3}, [%4];"
                 : "=r"(r0), "=r"(r1), "=r"(r2), "=r"(r3) : "r"(a));
}
__device__ __forceinline__ void mma16816(float& c0, float& c1, float& c2, float& c3,
                                         uint32_t a0, uint32_t a1, uint32_t a2, uint32_t a3,
                                         uint32_t b0, uint32_t b1) {
    asm volatile(
        "mma.sync.aligned.m16n8k16.row.col.f32.f16.f16.f32 "
        "{%0,%1,%2,%3}, {%4,%5,%6,%7}, {%8,%9}, {%0,%1,%2,%3};"
        : "+f"(c0), "+f"(c1), "+f"(c2), "+f"(c3)
        : "r"(a0), "r"(a1), "r"(a2), "r"(a3), "r"(b0), "r"(b1));
}

// ---------------------------------------------------------------------------
// Kernel 1: fp32 -> fp16 convert (row-major, cp.async-ready)
// ---------------------------------------------------------------------------
__global__ __launch_bounds__(256) void convert_kernel(const float* __restrict__ X) {
    const int gid = blockIdx.x * 256 + threadIdx.x;      // < 1048576 (8 elts each)
    const float4* s = reinterpret_cast<const float4*>(X) + (size_t)gid * 2;
    const float4 a = s[0];
    const float4 b = s[1];
    __half2 h0 = __floats2half2_rn(a.x, a.y);
    __half2 h1 = __floats2half2_rn(a.z, a.w);
    __half2 h2 = __floats2half2_rn(b.x, b.y);
    __half2 h3 = __floats2half2_rn(b.z, b.w);
    uint4 v;
    v.x = *reinterpret_cast<uint32_t*>(&h0);
    v.y = *reinterpret_cast<uint32_t*>(&h1);
    v.z = *reinterpret_cast<uint32_t*>(&h2);
    v.w = *reinterpret_cast<uint32_t*>(&h3);
    reinterpret_cast<uint4*>(g_h)[gid] = v;
}

// ---------------------------------------------------------------------------
// Kernel 2: split-K fp16 GEMM, cp.async 3-stage pipeline.
//   grid (SPLITS, 4): blockIdx.y -> (mt, nt) 2x2 tiles of 128x128.
//   U_p[tile] = A_h * B_h^T over this split's K-chunk (fp32 accumulate).
//   8 warps (2x4), each owns 64x32 (4x4 m16n8 tiles).
// ---------------------------------------------------------------------------
extern __shared__ unsigned char dsm[];

__global__ __launch_bounds__(256, 1) void gemm_kernel() {
    const int split = blockIdx.x;
    const int mt = blockIdx.y & 1;
    const int nt = blockIdx.y >> 1;
    const int t    = threadIdx.x;
    const int w    = t >> 5;
    const int lane = t & 31;
    const int wm   = w >> 2;      // 0..1
    const int wn   = w & 3;       // 0..3

    const uint32_t sb = smem_u32(dsm);
    const int chunk0 = split * CHUNK;

    const __half* gA = g_h + (size_t)(mt * 128) * DIM + chunk0;
    const __half* gB = g_h + (size_t)(nt * 128) * DIM + chunk0;

    float acc[4][4][4];
#pragma unroll
    for (int i = 0; i < 4; i++)
#pragma unroll
        for (int j = 0; j < 4; j++)
#pragma unroll
            for (int r = 0; r < 4; r++) acc[i][j][r] = 0.f;

    auto issue = [&](int kb, int st_idx) {
        const uint32_t st = sb + st_idx * STAGE;
        const int kcol = kb * KB;
#pragma unroll
        for (int i = 0; i < 8; i++) {
            const int idx  = t + 256 * i;
            const int tile = idx >> 10;          // 0 = A, 1 = B
            const int s2   = idx & 1023;
            const int row  = s2 >> 3;
            const int c    = s2 & 7;
            const __half* g = (tile ? gB : gA) + (size_t)row * DIM + kcol + c * 8;
            cpasync16(st + tile * TILE_SM + row * STRIDE + c * 16, g);
        }
        asm volatile("cp.async.commit_group;" ::: "memory");
    };

    issue(0, 0);
    issue(1, 1);

    const uint32_t a_ld = (uint32_t)(wm * 64 + (lane & 15)) * STRIDE + ((lane >> 4) & 1) * 16;
    const int bsel  = (lane >> 3) & 3;
    const uint32_t b_ld = (uint32_t)(wn * 32 + ((bsel >> 1) * 8) + (lane & 7)) * STRIDE
                        + (bsel & 1) * 16;

    int st_idx = 0;
    for (int kb = 0; kb < NKB; kb++) {
        if (kb + 2 < NKB) {
            issue(kb + 2, (st_idx + 2) % NSTAGE);
            asm volatile("cp.async.wait_group 2;" ::: "memory");
        } else if (kb + 1 < NKB) {
            asm volatile("cp.async.wait_group 1;" ::: "memory");
        } else {
            asm volatile("cp.async.wait_group 0;" ::: "memory");
        }
        __syncthreads();

        const uint32_t st = sb + st_idx * STAGE;
#pragma unroll
        for (int ks = 0; ks < 4; ks++) {
            const uint32_t ko = ks * 32;
            uint32_t af[4][4];
#pragma unroll
            for (int i = 0; i < 4; i++)
                ldm_x4(st + a_ld + (uint32_t)i * 16 * STRIDE + ko,
                       af[i][0], af[i][1], af[i][2], af[i][3]);
            uint32_t bf[2][4];
#pragma unroll
            for (int p = 0; p < 2; p++)
                ldm_x4(st + TILE_SM + b_ld + (uint32_t)p * 16 * STRIDE + ko,
                       bf[p][0], bf[p][1], bf[p][2], bf[p][3]);
#pragma unroll
            for (int i = 0; i < 4; i++)
#pragma unroll
                for (int j = 0; j < 4; j++) {
                    const int p = j >> 1, h = (j & 1) * 2;
                    mma16816(acc[i][j][0], acc[i][j][1], acc[i][j][2], acc[i][j][3],
                             af[i][0], af[i][1], af[i][2], af[i][3],
                             bf[p][h], bf[p][h + 1]);
                }
        }
        st_idx = (st_idx + 1) % NSTAGE;
    }

    float* out = g_part + ((size_t)split << 16);
    const int rbase = mt * 128 + wm * 64 + (lane >> 2);
    const int cbase = nt * 128 + wn * 32 + (lane & 3) * 2;
#pragma unroll
    for (int i = 0; i < 4; i++)
#pragma unroll
        for (int j = 0; j < 4; j++) {
            const int r0 = rbase + i * 16;
            const int c  = cbase + j * 8;
            *reinterpret_cast<float2*>(out + r0 * BB + c)       = make_float2(acc[i][j][0], acc[i][j][1]);
            *reinterpret_cast<float2*>(out + (r0 + 8) * BB + c) = make_float2(acc[i][j][2], acc[i][j][3]);
        }
}

// ---------------------------------------------------------------------------
// Kernel 3: G = sum_p U_p (ordered, deterministic); also resets g_count.
// ---------------------------------------------------------------------------
__global__ __launch_bounds__(256) void reduce_kernel() {
    const int idx = blockIdx.x * 256 + threadIdx.x;     // 0..16383 (float4 units)
    float4 acc = make_float4(0.f, 0.f, 0.f, 0.f);
    for (int p = 0; p < SPLITS; p++) {
        float4 v = reinterpret_cast<const float4*>(g_part + ((size_t)p << 16))[idx];
        acc.x += v.x; acc.y += v.y; acc.z += v.z; acc.w += v.w;
    }
    reinterpret_cast<float4*>(g_G)[idx] = acc;
    if (idx == 0) g_count = 0;
}

// ---------------------------------------------------------------------------
// Kernel 4: per-anchor triplet loss (ordered-pair identity) + fused final.
// Branch-free inner loop: Dimp[k] = Drow[k] for impostors, +1e30 otherwise,
// so relu(dab + m - Dimp[k]) vanishes for non-impostors. fp32 accumulation
// (4 independent accumulators), fp64 only at the 256-wide tree reduce.
// Counts are closed-form: cnt(a) = nPos(a) * nImp(a) via ballot popcounts.
// ---------------------------------------------------------------------------
__global__ __launch_bounds__(256) void loss_kernel(const int* __restrict__ mods,
                                                   float* __restrict__ out) {
    const int a = blockIdx.x;
    const int t = threadIdx.x;
    __shared__ float  Drow[BB];
    __shared__ float  Dimp[BB];
    __shared__ int    smod[BB];
    __shared__ int    wcnt[2][8];
    __shared__ double sacc[BB];
    __shared__ int    is_last;

    smod[t] = mods[t];
    __syncthreads();

    const int ma = smod[a];
    const float sqa = g_G[a * BB + a];
    const float sqb = g_G[t * BB + t];
    float d2 = sqa + sqb - 2.f * g_G[a * BB + t];
    d2 = fmaxf(d2, 0.f);
    const float dv = (d2 > 0.f) ? sqrtf(d2) : 0.f;
    Drow[t] = dv;
    const bool imp = (smod[t] != ma);
    const bool pos = (t != a) && !imp;
    Dimp[t] = imp ? dv : 1e30f;

    // ballot counts: impostors and positives
    const uint32_t bi = __ballot_sync(0xFFFFFFFFu, imp);
    const uint32_t bp = __ballot_sync(0xFFFFFFFFu, pos);
    if ((t & 31) == 0) { wcnt[0][t >> 5] = __popc(bi); wcnt[1][t >> 5] = __popc(bp); }
    __syncthreads();

    float a0 = 0.f, a1 = 0.f, a2 = 0.f, a3 = 0.f;
    if (pos) {
        const float dabm = Drow[t] + MARGIN;
#pragma unroll 8
        for (int k = 0; k < BB; k += 4) {
            a0 += fmaxf(dabm - Dimp[k + 0], 0.f);
            a1 += fmaxf(dabm - Dimp[k + 1], 0.f);
            a2 += fmaxf(dabm - Dimp[k + 2], 0.f);
            a3 += fmaxf(dabm - Dimp[k + 3], 0.f);
        }
    }
    sacc[t] = (double)((a0 + a1) + (a2 + a3));
    __syncthreads();
    for (int stride = 128; stride > 0; stride >>= 1) {
        if (t < stride) sacc[t] += sacc[t + stride];
        __syncthreads();
    }
    if (t == 0) {
        int nImp = 0, nPos = 0;
#pragma unroll
        for (int i = 0; i < 8; i++) { nImp += wcnt[0][i]; nPos += wcnt[1][i]; }
        g_lossp[a] = sacc[0];
        g_cntp[a]  = (double)nPos * (double)nImp;
    }

    // last-block-done election (threadFenceReduction pattern)
    __threadfence();
    if (t == 0) {
        int old = atomicAdd(&g_count, 1);
        is_last = (old == BB - 1);
    }
    __syncthreads();
    if (is_last) {
        __threadfence();
        sacc[t] = g_lossp[t];
        __shared__ double scnt2[BB];
        scnt2[t] = g_cntp[t];
        __syncthreads();
        for (int stride = 128; stride > 0; stride >>= 1) {
            if (t < stride) { sacc[t] += sacc[t + stride]; scnt2[t] += scnt2[t + stride]; }
            __syncthreads();
        }
        if (t == 0) out[0] = (float)(sacc[0] / scnt2[0]);
    }
}

// ---------------------------------------------------------------------------
extern "C" void kernel_launch(void* const* d_in, const int* in_sizes, int n_in,
                              void* d_out, int out_size) {
    const float* X    = (const float*)d_in[0];
    const int*   mods = (const int*)  d_in[1];
    (void)in_sizes; (void)n_in; (void)out_size;

    cudaFuncSetAttribute(gemm_kernel, cudaFuncAttributeMaxDynamicSharedMemorySize, SMEM_TOTAL);

    convert_kernel<<<(BB * DIM / 8) / 256, 256>>>(X);
    gemm_kernel<<<dim3(SPLITS, 4), 256, SMEM_TOTAL>>>();
    reduce_kernel<<<(BB * BB / 4) / 256, 256>>>();
    loss_kernel<<<BB, 256>>>(mods, (float*)d_out);
}

// round 7
// speedup vs baseline: 5.0379x; 1.0416x over previous
#include <cuda_runtime.h>
#include <cuda_fp16.h>
#include <math.h>
#include <stdint.h>

// ---------------------------------------------------------------------------
// Problem constants
// ---------------------------------------------------------------------------
#define BB       256
#define DIM      32768
#define SPLITS   32
#define CHUNK    (DIM / SPLITS)     // 1024 fp16 cols per split
#define KB       64                 // k-block (fp16 cols per smem stage) = 128 B/row
#define NKB      (CHUNK / KB)       // 16
#define STRIDE   144                // smem row stride (128 B data + 16 B pad)
#define TILE_SM  (128 * STRIDE)     // 18432 B per tile
#define STAGE    (2 * TILE_SM)      // 36864 B (A tile + B tile)
#define NSTAGE   3
#define SMEM_TOTAL (NSTAGE * STAGE) // 110592 B
#define MARGIN   0.003f

// ---------------------------------------------------------------------------
// Static device scratch (no allocations anywhere)
// ---------------------------------------------------------------------------
__device__ __align__(16) __half g_h[BB * DIM];     // 16 MB fp16 copy of X
__device__ float  g_part[SPLITS * BB * BB];        // 8 MB split-K partials
__device__ float  g_G[BB * BB];
__device__ float  g_sq[BB];                        // diag(G) = squared norms
__device__ double g_lossp[BB];
__device__ double g_cntp[BB];
__device__ int    g_count;

// ---------------------------------------------------------------------------
// Helpers
// ---------------------------------------------------------------------------
__device__ __forceinline__ uint32_t smem_u32(const void* p) {
    uint32_t a;
    asm("{ .reg .u64 t; cvta.to.shared.u64 t, %1; cvt.u32.u64 %0, t; }" : "=r"(a) : "l"(p));
    return a;
}
__device__ __forceinline__ void cpasync16(uint32_t s, const void* g) {
    asm volatile("cp.async.cg.shared.global [%0], [%1], 16;" :: "r"(s), "l"(g) : "memory");
}
__device__ __forceinline__ void ldm_x4(uint32_t a, uint32_t& r0, uint32_t& r1,
                                       uint32_t& r2, uint32_t& r3) {
    asm volatile("ldmatrix.sync.aligned.m8n8.x4.shared.b16 {%0,%1,%2,%3}, [%4];"
                 : "=r"(r0), "=r"(r1), "=r"(r2), "=r"(r3) : "r"(a));
}
__device__ __forceinline__ void mma16816(float& c0, float& c1, float& c2, float& c3,
                                         uint32_t a0, uint32_t a1, uint32_t a2, uint32_t a3,
                                         uint32_t b0, uint32_t b1) {
    asm volatile(
        "mma.sync.aligned.m16n8k16.row.col.f32.f16.f16.f32 "
        "{%0,%1,%2,%3}, {%4,%5,%6,%7}, {%8,%9}, {%0,%1,%2,%3};"
        : "+f"(c0), "+f"(c1), "+f"(c2), "+f"(c3)
        : "r"(a0), "r"(a1), "r"(a2), "r"(a3), "r"(b0), "r"(b1));
}

// ---------------------------------------------------------------------------
// Kernel 1: fp32 -> fp16 convert (row-major, cp.async-ready)
// ---------------------------------------------------------------------------
__global__ __launch_bounds__(256) void convert_kernel(const float* __restrict__ X) {
    const int gid = blockIdx.x * 256 + threadIdx.x;      // < 1048576 (8 elts each)
    const float4* s = reinterpret_cast<const float4*>(X) + (size_t)gid * 2;
    const float4 a = s[0];
    const float4 b = s[1];
    __half2 h0 = __floats2half2_rn(a.x, a.y);
    __half2 h1 = __floats2half2_rn(a.z, a.w);
    __half2 h2 = __floats2half2_rn(b.x, b.y);
    __half2 h3 = __floats2half2_rn(b.z, b.w);
    uint4 v;
    v.x = *reinterpret_cast<uint32_t*>(&h0);
    v.y = *reinterpret_cast<uint32_t*>(&h1);
    v.z = *reinterpret_cast<uint32_t*>(&h2);
    v.w = *reinterpret_cast<uint32_t*>(&h3);
    reinterpret_cast<uint4*>(g_h)[gid] = v;
}

// ---------------------------------------------------------------------------
// Kernel 2: split-K fp16 GEMM, cp.async 3-stage pipeline.
//   grid (SPLITS, 4): blockIdx.y -> (mt, nt) 2x2 tiles of 128x128.
//   8 warps (2x4), each owns 64x32 (4x4 m16n8 tiles).
// ---------------------------------------------------------------------------
extern __shared__ unsigned char dsm[];

__global__ __launch_bounds__(256, 1) void gemm_kernel() {
    const int split = blockIdx.x;
    const int mt = blockIdx.y & 1;
    const int nt = blockIdx.y >> 1;
    const int t    = threadIdx.x;
    const int w    = t >> 5;
    const int lane = t & 31;
    const int wm   = w >> 2;
    const int wn   = w & 3;

    const uint32_t sb = smem_u32(dsm);
    const int chunk0 = split * CHUNK;

    const __half* gA = g_h + (size_t)(mt * 128) * DIM + chunk0;
    const __half* gB = g_h + (size_t)(nt * 128) * DIM + chunk0;

    float acc[4][4][4];
#pragma unroll
    for (int i = 0; i < 4; i++)
#pragma unroll
        for (int j = 0; j < 4; j++)
#pragma unroll
            for (int r = 0; r < 4; r++) acc[i][j][r] = 0.f;

    auto issue = [&](int kb, int st_idx) {
        const uint32_t st = sb + st_idx * STAGE;
        const int kcol = kb * KB;
#pragma unroll
        for (int i = 0; i < 8; i++) {
            const int idx  = t + 256 * i;
            const int tile = idx >> 10;
            const int s2   = idx & 1023;
            const int row  = s2 >> 3;
            const int c    = s2 & 7;
            const __half* g = (tile ? gB : gA) + (size_t)row * DIM + kcol + c * 8;
            cpasync16(st + tile * TILE_SM + row * STRIDE + c * 16, g);
        }
        asm volatile("cp.async.commit_group;" ::: "memory");
    };

    issue(0, 0);
    issue(1, 1);

    const uint32_t a_ld = (uint32_t)(wm * 64 + (lane & 15)) * STRIDE + ((lane >> 4) & 1) * 16;
    const int bsel  = (lane >> 3) & 3;
    const uint32_t b_ld = (uint32_t)(wn * 32 + ((bsel >> 1) * 8) + (lane & 7)) * STRIDE
                        + (bsel & 1) * 16;

    int st_idx = 0;
    for (int kb = 0; kb < NKB; kb++) {
        if (kb + 2 < NKB) {
            issue(kb + 2, (st_idx + 2) % NSTAGE);
            asm volatile("cp.async.wait_group 2;" ::: "memory");
        } else if (kb + 1 < NKB) {
            asm volatile("cp.async.wait_group 1;" ::: "memory");
        } else {
            asm volatile("cp.async.wait_group 0;" ::: "memory");
        }
        __syncthreads();

        const uint32_t st = sb + st_idx * STAGE;
#pragma unroll
        for (int ks = 0; ks < 4; ks++) {
            const uint32_t ko = ks * 32;
            uint32_t af[4][4];
#pragma unroll
            for (int i = 0; i < 4; i++)
                ldm_x4(st + a_ld + (uint32_t)i * 16 * STRIDE + ko,
                       af[i][0], af[i][1], af[i][2], af[i][3]);
            uint32_t bf[2][4];
#pragma unroll
            for (int p = 0; p < 2; p++)
                ldm_x4(st + TILE_SM + b_ld + (uint32_t)p * 16 * STRIDE + ko,
                       bf[p][0], bf[p][1], bf[p][2], bf[p][3]);
#pragma unroll
            for (int i = 0; i < 4; i++)
#pragma unroll
                for (int j = 0; j < 4; j++) {
                    const int p = j >> 1, h = (j & 1) * 2;
                    mma16816(acc[i][j][0], acc[i][j][1], acc[i][j][2], acc[i][j][3],
                             af[i][0], af[i][1], af[i][2], af[i][3],
                             bf[p][h], bf[p][h + 1]);
                }
        }
        st_idx = (st_idx + 1) % NSTAGE;
    }

    float* out = g_part + ((size_t)split << 16);
    const int rbase = mt * 128 + wm * 64 + (lane >> 2);
    const int cbase = nt * 128 + wn * 32 + (lane & 3) * 2;
#pragma unroll
    for (int i = 0; i < 4; i++)
#pragma unroll
        for (int j = 0; j < 4; j++) {
            const int r0 = rbase + i * 16;
            const int c  = cbase + j * 8;
            *reinterpret_cast<float2*>(out + r0 * BB + c)       = make_float2(acc[i][j][0], acc[i][j][1]);
            *reinterpret_cast<float2*>(out + (r0 + 8) * BB + c) = make_float2(acc[i][j][2], acc[i][j][3]);
        }
}

// ---------------------------------------------------------------------------
// Kernel 3: G = sum_p U_p (ordered); extracts diag -> g_sq; resets g_count.
// ---------------------------------------------------------------------------
__global__ __launch_bounds__(256) void reduce_kernel() {
    const int idx = blockIdx.x * 256 + threadIdx.x;     // float4 unit index
    float4 acc = make_float4(0.f, 0.f, 0.f, 0.f);
    for (int p = 0; p < SPLITS; p++) {
        float4 v = reinterpret_cast<const float4*>(g_part + ((size_t)p << 16))[idx];
        acc.x += v.x; acc.y += v.y; acc.z += v.z; acc.w += v.w;
    }
    reinterpret_cast<float4*>(g_G)[idx] = acc;
    const int row = idx >> 6;            // BB/4 = 64 units per row
    const int c0  = (idx & 63) * 4;
    if (row >= c0 && row < c0 + 4) {     // this unit holds diag element (row,row)
        const float d = (row - c0 == 0) ? acc.x : (row - c0 == 1) ? acc.y
                      : (row - c0 == 2) ? acc.z : acc.w;
        g_sq[row] = d;
    }
    if (idx == 0) g_count = 0;
}

// ---------------------------------------------------------------------------
// Kernel 4: per-anchor triplet loss, impostor-major with compacted positives.
// loss(a) = sum_{k imp} sum_{b pos} relu((D_ab + m) - D_ak)
// Thread t = candidate k (~192 active impostors). Positives are compacted
// into pv[] (pv[i] = D_ab + m) via deterministic ballot prefix-scan, padded
// with -1e30 so relu self-masks. cnt(a) = nPos*nImp closed form.
// fp32 accumulation (2 lanes), fp64 at the 256-wide tree; fused final
// reduction via last-block election.
// ---------------------------------------------------------------------------
__global__ __launch_bounds__(256) void loss_kernel(const int* __restrict__ mods,
                                                   float* __restrict__ out) {
    const int a = blockIdx.x;
    const int t = threadIdx.x;
    const int w = t >> 5;
    const int lane = t & 31;
    __shared__ int    smod[BB];
    __shared__ float  pv[BB + 8];
    __shared__ int    wpos[8], wimp[8];
    __shared__ double dacc[BB];
    __shared__ int    is_last;

    smod[t] = mods[t];
    __syncthreads();

    const int ma = smod[a];
    const float sqa = g_sq[a];
    const float sqt = g_sq[t];
    float d2 = sqa + sqt - 2.f * g_G[a * BB + t];
    d2 = fmaxf(d2, 0.f);
    const float dv = (d2 > 0.f) ? sqrtf(d2) : 0.f;

    const bool imp = (smod[t] != ma);
    const bool pos = (t != a) && !imp;

    const uint32_t bp = __ballot_sync(0xFFFFFFFFu, pos);
    const uint32_t bi = __ballot_sync(0xFFFFFFFFu, imp);
    if (lane == 0) { wpos[w] = __popc(bp); wimp[w] = __popc(bi); }
    __syncthreads();

    int base = 0, nPos = 0, nImp = 0;
#pragma unroll
    for (int i = 0; i < 8; i++) {
        if (i < w) base += wpos[i];
        nPos += wpos[i];
        nImp += wimp[i];
    }
    if (pos) pv[base + __popc(bp & ((1u << lane) - 1u))] = dv + MARGIN;
    if (t < 8) pv[nPos + t] = -1e30f;   // padding: relu self-masks
    __syncthreads();

    float a0 = 0.f, a1 = 0.f;
    if (imp) {
        const float dak = dv;
        const int n8 = (nPos + 7) & ~7;
#pragma unroll 1
        for (int i = 0; i < n8; i += 8) {
            a0 += fmaxf(pv[i + 0] - dak, 0.f);
            a1 += fmaxf(pv[i + 1] - dak, 0.f);
            a0 += fmaxf(pv[i + 2] - dak, 0.f);
            a1 += fmaxf(pv[i + 3] - dak, 0.f);
            a0 += fmaxf(pv[i + 4] - dak, 0.f);
            a1 += fmaxf(pv[i + 5] - dak, 0.f);
            a0 += fmaxf(pv[i + 6] - dak, 0.f);
            a1 += fmaxf(pv[i + 7] - dak, 0.f);
        }
    }
    dacc[t] = (double)(a0 + a1);
    __syncthreads();
    for (int stride = 128; stride > 0; stride >>= 1) {
        if (t < stride) dacc[t] += dacc[t + stride];
        __syncthreads();
    }
    if (t == 0) {
        g_lossp[a] = dacc[0];
        g_cntp[a]  = (double)nPos * (double)nImp;
    }

    __threadfence();
    if (t == 0) {
        int old = atomicAdd(&g_count, 1);
        is_last = (old == BB - 1);
    }
    __syncthreads();
    if (is_last) {
        __threadfence();
        __shared__ double scnt2[BB];
        dacc[t]  = g_lossp[t];
        scnt2[t] = g_cntp[t];
        __syncthreads();
        for (int stride = 128; stride > 0; stride >>= 1) {
            if (t < stride) { dacc[t] += dacc[t + stride]; scnt2[t] += scnt2[t + stride]; }
            __syncthreads();
        }
        if (t == 0) out[0] = (float)(dacc[0] / scnt2[0]);
    }
}

// ---------------------------------------------------------------------------
extern "C" void kernel_launch(void* const* d_in, const int* in_sizes, int n_in,
                              void* d_out, int out_size) {
    const float* X    = (const float*)d_in[0];
    const int*   mods = (const int*)  d_in[1];
    (void)in_sizes; (void)n_in; (void)out_size;

    cudaFuncSetAttribute(gemm_kernel, cudaFuncAttributeMaxDynamicSharedMemorySize, SMEM_TOTAL);

    convert_kernel<<<(BB * DIM / 8) / 256, 256>>>(X);
    gemm_kernel<<<dim3(SPLITS, 4), 256, SMEM_TOTAL>>>();
    reduce_kernel<<<(BB * BB / 4) / 256, 256>>>();
    loss_kernel<<<BB, 256>>>(mods, (float*)d_out);
}